// round 5
// baseline (speedup 1.0000x reference)
#include <cuda_runtime.h>
#include <cuda_fp16.h>
#include <math.h>
#include <stdint.h>

#define NN 100000
#define NE 1600000
#define ET (NE + NN)
#define LRELU 0.2f

// ---------- scratch ----------
__device__ __half g_h[(size_t)NN * 128];     // post-GEMM features (fp16)
__device__ __half g_feat[(size_t)NN * 128];  // post-LN features (fp16)
__device__ float g_als[(size_t)NN * 8];
__device__ float g_ald[(size_t)NN * 8];
__device__ int   g_rowptr[NN + 1];
__device__ int   g_cnt[NN];
__device__ int   g_srcs[ET];
__device__ int   g_part[128];

// ---------------------- CSR build ----------------------
__global__ void k_init_cnt(int n) {
    int i = blockIdx.x * blockDim.x + threadIdx.x;
    if (i < n) g_cnt[i] = 1;
}
__global__ void k_count(const int* __restrict__ dst, int e) {
    int i = blockIdx.x * blockDim.x + threadIdx.x;
    if (i < e) atomicAdd(&g_cnt[dst[i]], 1);
}
__global__ void k_scan1(int n) {
    __shared__ int sh[1024];
    int tid = threadIdx.x;
    int i = blockIdx.x * 1024 + tid;
    int v = (i < n) ? g_cnt[i] : 0;
    sh[tid] = v;
    __syncthreads();
    #pragma unroll
    for (int o = 1; o < 1024; o <<= 1) {
        int t = (tid >= o) ? sh[tid - o] : 0;
        __syncthreads();
        sh[tid] += t;
        __syncthreads();
    }
    if (i < n) g_rowptr[i] = sh[tid] - v;
    if (tid == 1023) g_part[blockIdx.x] = sh[1023];
}
__global__ void k_scan2(int nb) {
    __shared__ int sh[128];
    int tid = threadIdx.x;
    int v = (tid < nb) ? g_part[tid] : 0;
    sh[tid] = v;
    __syncthreads();
    #pragma unroll
    for (int o = 1; o < 128; o <<= 1) {
        int t = (tid >= o) ? sh[tid - o] : 0;
        __syncthreads();
        sh[tid] += t;
        __syncthreads();
    }
    if (tid < nb) g_part[tid] = sh[tid] - v;
}
// scan finalize + self-loop placement + cursor init (fused)
__global__ void k_scan3(int n, int etot) {
    int i = blockIdx.x * 1024 + threadIdx.x;
    if (i < n) {
        int p = g_rowptr[i] + g_part[blockIdx.x];
        g_rowptr[i] = p;
        g_srcs[p] = i;          // self loop first
        g_cnt[i] = p + 1;       // scatter cursor
    }
    if (i == 0) g_rowptr[n] = etot;
}
__global__ void k_scatter(const int* __restrict__ src, const int* __restrict__ dst, int e) {
    int i = blockIdx.x * blockDim.x + threadIdx.x;
    if (i < e) {
        int pos = atomicAdd(&g_cnt[dst[i]], 1);
        g_srcs[pos] = src[i];
    }
}

// ---------------------- fp16 mma helper ----------------------
#define MMA_F16(d, a, b) \
    asm volatile("mma.sync.aligned.m16n8k16.row.col.f32.f16.f16.f32 " \
        "{%0,%1,%2,%3}, {%4,%5,%6,%7}, {%8,%9}, {%0,%1,%2,%3};" \
        : "+f"((d)[0]), "+f"((d)[1]), "+f"((d)[2]), "+f"((d)[3]) \
        : "r"((a)[0]), "r"((a)[1]), "r"((a)[2]), "r"((a)[3]), \
          "r"((b)[0]), "r"((b)[1]))

// stage A tile [128 rows x 128 k] into As (half, row stride 136)
template <typename TA>
__device__ __forceinline__ void stage_A(const TA* __restrict__ A, uint32_t* As_u32,
                                        int row0, int n, int tid) {
    __half* As = (__half*)As_u32;
    #pragma unroll
    for (int l = 0; l < 8; l++) {
        int idx = tid + l * 256;          // 0..2047
        int r = idx >> 4, kq = idx & 15;  // kq*8 = k
        int gr = row0 + r;
        uint4 u;
        if (gr < n) {
            const float4 z4 = make_float4(0.f, 0.f, 0.f, 0.f);
            (void)z4;
            // load 8 values
            float v[8];
            if (sizeof(TA) == 4) {
                const float* Af = (const float*)A;
                float4 f0 = *(const float4*)(Af + (size_t)gr * 128 + kq * 8);
                float4 f1 = *(const float4*)(Af + (size_t)gr * 128 + kq * 8 + 4);
                v[0]=f0.x; v[1]=f0.y; v[2]=f0.z; v[3]=f0.w;
                v[4]=f1.x; v[5]=f1.y; v[6]=f1.z; v[7]=f1.w;
                __half2 h0 = __floats2half2_rn(v[0], v[1]);
                __half2 h1 = __floats2half2_rn(v[2], v[3]);
                __half2 h2 = __floats2half2_rn(v[4], v[5]);
                __half2 h3 = __floats2half2_rn(v[6], v[7]);
                u.x = *(uint32_t*)&h0; u.y = *(uint32_t*)&h1;
                u.z = *(uint32_t*)&h2; u.w = *(uint32_t*)&h3;
            } else {
                u = *(const uint4*)((const __half*)A + (size_t)gr * 128 + kq * 8);
            }
        } else {
            u = make_uint4(0, 0, 0, 0);
        }
        *(uint4*)(As + r * 136 + kq * 8) = u;
    }
}

// ---------------------- fp16 TC GEMM 128x128 + attn coefs (8 heads x 16) ----------------------
template <typename TA>
__global__ __launch_bounds__(256) void k_gemm_attn8_f16(
    const TA* __restrict__ A, const float* __restrict__ W,
    const float* __restrict__ asr, const float* __restrict__ adr,
    __half* __restrict__ H, float* __restrict__ als, float* __restrict__ ald, int n)
{
    __shared__ __align__(16) uint32_t As_u[128 * 68];  // half [128][136]
    __shared__ __align__(16) uint32_t Bs_u[128 * 68];  // half [col 128][k 136] (W transposed)
    __half* As = (__half*)As_u;
    __half* Bs = (__half*)Bs_u;
    int tid = threadIdx.x;
    int wid = tid >> 5, lane = tid & 31;
    int warp_m = wid >> 1, warp_n = wid & 1;
    int g = lane >> 2, c = lane & 3;
    int row0 = blockIdx.x * 128;

    stage_A<TA>(A, As_u, row0, n, tid);
    // stage W transposed: Bs[col][k]
    #pragma unroll
    for (int l = 0; l < 16; l++) {
        int idx = tid + l * 256;          // 0..4095
        int k = idx >> 5, n0 = (idx & 31) * 4;
        float4 v = *(const float4*)(W + (size_t)k * 128 + n0);
        Bs[(n0 + 0) * 136 + k] = __float2half_rn(v.x);
        Bs[(n0 + 1) * 136 + k] = __float2half_rn(v.y);
        Bs[(n0 + 2) * 136 + k] = __float2half_rn(v.z);
        Bs[(n0 + 3) * 136 + k] = __float2half_rn(v.w);
    }
    __syncthreads();

    float acc[2][8][4];
    #pragma unroll
    for (int mt = 0; mt < 2; mt++)
        #pragma unroll
        for (int nt = 0; nt < 8; nt++)
            #pragma unroll
            for (int j = 0; j < 4; j++) acc[mt][nt][j] = 0.f;

    #pragma unroll
    for (int ks = 0; ks < 8; ks++) {
        int kb = ks * 16 + c * 2;
        uint32_t bf[8][2];
        #pragma unroll
        for (int nt = 0; nt < 8; nt++) {
            int col = warp_n * 64 + nt * 8 + g;
            bf[nt][0] = *(uint32_t*)(Bs + col * 136 + kb);
            bf[nt][1] = *(uint32_t*)(Bs + col * 136 + kb + 8);
        }
        #pragma unroll
        for (int mt = 0; mt < 2; mt++) {
            int row = warp_m * 32 + mt * 16 + g;
            uint32_t af[4];
            af[0] = *(uint32_t*)(As + row * 136 + kb);
            af[1] = *(uint32_t*)(As + (row + 8) * 136 + kb);
            af[2] = *(uint32_t*)(As + row * 136 + kb + 8);
            af[3] = *(uint32_t*)(As + (row + 8) * 136 + kb + 8);
            #pragma unroll
            for (int nt = 0; nt < 8; nt++) MMA_F16(acc[mt][nt], af, bf[nt]);
        }
    }

    // epilogue: H (fp16) + per-head attn coefficients
    #pragma unroll
    for (int mt = 0; mt < 2; mt++) {
        int r_lo = row0 + warp_m * 32 + mt * 16 + g;
        int r_hi = r_lo + 8;
        float sA0[4] = {0, 0, 0, 0}, sA1[4] = {0, 0, 0, 0};
        float sD0[4] = {0, 0, 0, 0}, sD1[4] = {0, 0, 0, 0};
        #pragma unroll
        for (int nt = 0; nt < 8; nt++) {
            int col = warp_n * 64 + nt * 8 + c * 2;
            int hh = nt >> 1;
            float as0 = asr[col], as1 = asr[col + 1];
            float ad0 = adr[col], ad1 = adr[col + 1];
            float* d = acc[mt][nt];
            sA0[hh] = fmaf(d[0], as0, fmaf(d[1], as1, sA0[hh]));
            sA1[hh] = fmaf(d[2], as0, fmaf(d[3], as1, sA1[hh]));
            sD0[hh] = fmaf(d[0], ad0, fmaf(d[1], ad1, sD0[hh]));
            sD1[hh] = fmaf(d[2], ad0, fmaf(d[3], ad1, sD1[hh]));
            if (r_lo < n) *(__half2*)(H + (size_t)r_lo * 128 + col) = __floats2half2_rn(d[0], d[1]);
            if (r_hi < n) *(__half2*)(H + (size_t)r_hi * 128 + col) = __floats2half2_rn(d[2], d[3]);
        }
        #pragma unroll
        for (int hh = 0; hh < 4; hh++) {
            sA0[hh] += __shfl_xor_sync(0xFFFFFFFFu, sA0[hh], 1);
            sA0[hh] += __shfl_xor_sync(0xFFFFFFFFu, sA0[hh], 2);
            sA1[hh] += __shfl_xor_sync(0xFFFFFFFFu, sA1[hh], 1);
            sA1[hh] += __shfl_xor_sync(0xFFFFFFFFu, sA1[hh], 2);
            sD0[hh] += __shfl_xor_sync(0xFFFFFFFFu, sD0[hh], 1);
            sD0[hh] += __shfl_xor_sync(0xFFFFFFFFu, sD0[hh], 2);
            sD1[hh] += __shfl_xor_sync(0xFFFFFFFFu, sD1[hh], 1);
            sD1[hh] += __shfl_xor_sync(0xFFFFFFFFu, sD1[hh], 2);
        }
        if (c == 0) {
            #pragma unroll
            for (int hh = 0; hh < 4; hh++) {
                int hgl = warp_n * 4 + hh;
                if (r_lo < n) { als[(size_t)r_lo * 8 + hgl] = sA0[hh]; ald[(size_t)r_lo * 8 + hgl] = sD0[hh]; }
                if (r_hi < n) { als[(size_t)r_hi * 8 + hgl] = sA1[hh]; ald[(size_t)r_hi * 8 + hgl] = sD1[hh]; }
            }
        }
    }
}

// ---------------------- fp16 TC GEMM 128x64 + attn coefs (1 head x 64) ----------------------
__global__ __launch_bounds__(256) void k_gemm_attn1_f16(
    const __half* __restrict__ A, const float* __restrict__ W,
    const float* __restrict__ asr, const float* __restrict__ adr,
    __half* __restrict__ H, float* __restrict__ als, float* __restrict__ ald, int n)
{
    __shared__ __align__(16) uint32_t As_u[128 * 68];
    __shared__ __align__(16) uint32_t Bs_u[64 * 68];   // half [col 64][k 136]
    __half* As = (__half*)As_u;
    __half* Bs = (__half*)Bs_u;
    int tid = threadIdx.x;
    int wid = tid >> 5, lane = tid & 31;
    int g = lane >> 2, c = lane & 3;
    int row0 = blockIdx.x * 128;

    stage_A<__half>(A, As_u, row0, n, tid);
    #pragma unroll
    for (int l = 0; l < 8; l++) {
        int idx = tid + l * 256;          // 0..2047
        int k = idx >> 4, n0 = (idx & 15) * 4;
        float4 v = *(const float4*)(W + (size_t)k * 64 + n0);
        Bs[(n0 + 0) * 136 + k] = __float2half_rn(v.x);
        Bs[(n0 + 1) * 136 + k] = __float2half_rn(v.y);
        Bs[(n0 + 2) * 136 + k] = __float2half_rn(v.z);
        Bs[(n0 + 3) * 136 + k] = __float2half_rn(v.w);
    }
    __syncthreads();

    float acc[8][4];
    #pragma unroll
    for (int nt = 0; nt < 8; nt++)
        #pragma unroll
        for (int j = 0; j < 4; j++) acc[nt][j] = 0.f;

    #pragma unroll
    for (int ks = 0; ks < 8; ks++) {
        int kb = ks * 16 + c * 2;
        int row = wid * 16 + g;
        uint32_t af[4];
        af[0] = *(uint32_t*)(As + row * 136 + kb);
        af[1] = *(uint32_t*)(As + (row + 8) * 136 + kb);
        af[2] = *(uint32_t*)(As + row * 136 + kb + 8);
        af[3] = *(uint32_t*)(As + (row + 8) * 136 + kb + 8);
        #pragma unroll
        for (int nt = 0; nt < 8; nt++) {
            int col = nt * 8 + g;
            uint32_t bf[2];
            bf[0] = *(uint32_t*)(Bs + col * 136 + kb);
            bf[1] = *(uint32_t*)(Bs + col * 136 + kb + 8);
            MMA_F16(acc[nt], af, bf);
        }
    }

    int r_lo = row0 + wid * 16 + g;
    int r_hi = r_lo + 8;
    float sA0 = 0.f, sA1 = 0.f, sD0 = 0.f, sD1 = 0.f;
    #pragma unroll
    for (int nt = 0; nt < 8; nt++) {
        int col = nt * 8 + c * 2;
        float as0 = asr[col], as1 = asr[col + 1];
        float ad0 = adr[col], ad1 = adr[col + 1];
        float* d = acc[nt];
        sA0 = fmaf(d[0], as0, fmaf(d[1], as1, sA0));
        sA1 = fmaf(d[2], as0, fmaf(d[3], as1, sA1));
        sD0 = fmaf(d[0], ad0, fmaf(d[1], ad1, sD0));
        sD1 = fmaf(d[2], ad0, fmaf(d[3], ad1, sD1));
        if (r_lo < n) *(__half2*)(H + (size_t)r_lo * 64 + col) = __floats2half2_rn(d[0], d[1]);
        if (r_hi < n) *(__half2*)(H + (size_t)r_hi * 64 + col) = __floats2half2_rn(d[2], d[3]);
    }
    sA0 += __shfl_xor_sync(0xFFFFFFFFu, sA0, 1); sA0 += __shfl_xor_sync(0xFFFFFFFFu, sA0, 2);
    sA1 += __shfl_xor_sync(0xFFFFFFFFu, sA1, 1); sA1 += __shfl_xor_sync(0xFFFFFFFFu, sA1, 2);
    sD0 += __shfl_xor_sync(0xFFFFFFFFu, sD0, 1); sD0 += __shfl_xor_sync(0xFFFFFFFFu, sD0, 2);
    sD1 += __shfl_xor_sync(0xFFFFFFFFu, sD1, 1); sD1 += __shfl_xor_sync(0xFFFFFFFFu, sD1, 2);
    if (c == 0) {
        if (r_lo < n) { als[r_lo] = sA0; ald[r_lo] = sD0; }
        if (r_hi < n) { als[r_hi] = sA1; ald[r_hi] = sD1; }
    }
}

// ---------------------- aggregation (8 heads x 16) + fused LN+ReLU, fp16 out ----------------------
__global__ __launch_bounds__(256) void k_agg8(
    const __half* __restrict__ H, const float* __restrict__ als,
    const float* __restrict__ ald, const float* __restrict__ bias,
    const float* __restrict__ lng, const float* __restrict__ lnb,
    __half* __restrict__ out, int n)
{
    int w = (blockIdx.x * blockDim.x + threadIdx.x) >> 5;
    if (w >= n) return;
    int lane = threadIdx.x & 31;
    int s = g_rowptr[w], e2 = g_rowptr[w + 1];
    int hd = lane >> 2;
    int d0 = lane * 4;
    float myald = ald[(size_t)w * 8 + (lane & 7)];
    float denom = 0.f;
    float ax = 0.f, ay = 0.f, az = 0.f, aw = 0.f;

    int i = s;
    for (; i + 4 <= e2; i += 4) {
        int sv[4];
        #pragma unroll
        for (int j = 0; j < 4; j++) sv[j] = g_srcs[i + j];
        float wv[4] = {0.f, 0.f, 0.f, 0.f};
        if (lane < 8) {
            float xv[4];
            #pragma unroll
            for (int j = 0; j < 4; j++) xv[j] = als[(size_t)sv[j] * 8 + lane] + myald;
            #pragma unroll
            for (int j = 0; j < 4; j++) {
                float x = (xv[j] > 0.f) ? xv[j] : LRELU * xv[j];
                wv[j] = __expf(x);
                denom += wv[j];
            }
        }
        uint2 raw[4];
        #pragma unroll
        for (int j = 0; j < 4; j++) raw[j] = *(const uint2*)(H + (size_t)sv[j] * 128 + d0);
        #pragma unroll
        for (int j = 0; j < 4; j++) {
            float a = __shfl_sync(0xFFFFFFFFu, wv[j], hd);
            float2 f01 = __half22float2(*(__half2*)&raw[j].x);
            float2 f23 = __half22float2(*(__half2*)&raw[j].y);
            ax = fmaf(a, f01.x, ax); ay = fmaf(a, f01.y, ay);
            az = fmaf(a, f23.x, az); aw = fmaf(a, f23.y, aw);
        }
    }
    for (; i < e2; ++i) {
        int s0 = g_srcs[i];
        float w0 = 0.f;
        if (lane < 8) {
            float x0 = als[(size_t)s0 * 8 + lane] + myald;
            x0 = (x0 > 0.f) ? x0 : LRELU * x0;
            w0 = __expf(x0);
            denom += w0;
        }
        float a0 = __shfl_sync(0xFFFFFFFFu, w0, hd);
        uint2 raw = *(const uint2*)(H + (size_t)s0 * 128 + d0);
        float2 f01 = __half22float2(*(__half2*)&raw.x);
        float2 f23 = __half22float2(*(__half2*)&raw.y);
        ax = fmaf(a0, f01.x, ax); ay = fmaf(a0, f01.y, ay);
        az = fmaf(a0, f23.x, az); aw = fmaf(a0, f23.y, aw);
    }

    float inv = 1.f / __shfl_sync(0xFFFFFFFFu, denom, hd);
    float4 bv = *(const float4*)(bias + d0);
    float ox = fmaf(ax, inv, bv.x);
    float oy = fmaf(ay, inv, bv.y);
    float oz = fmaf(az, inv, bv.z);
    float ow = fmaf(aw, inv, bv.w);

    // fused LayerNorm + ReLU
    float sm = ox + oy + oz + ow;
    #pragma unroll
    for (int o = 16; o; o >>= 1) sm += __shfl_xor_sync(0xFFFFFFFFu, sm, o);
    float mu = sm * (1.f / 128.f);
    float dx = ox - mu, dy = oy - mu, dz = oz - mu, dw = ow - mu;
    float q = dx * dx + dy * dy + dz * dz + dw * dw;
    #pragma unroll
    for (int o = 16; o; o >>= 1) q += __shfl_xor_sync(0xFFFFFFFFu, q, o);
    float rstd = rsqrtf(q * (1.f / 128.f) + 1e-5f);
    float4 gg = *(const float4*)(lng + d0);
    float4 bb = *(const float4*)(lnb + d0);
    ox = fmaxf(fmaf(dx * rstd, gg.x, bb.x), 0.f);
    oy = fmaxf(fmaf(dy * rstd, gg.y, bb.y), 0.f);
    oz = fmaxf(fmaf(dz * rstd, gg.z, bb.z), 0.f);
    ow = fmaxf(fmaf(dw * rstd, gg.w, bb.w), 0.f);

    __half2 h01 = __floats2half2_rn(ox, oy);
    __half2 h23 = __floats2half2_rn(oz, ow);
    uint2 packed = {*(uint32_t*)&h01, *(uint32_t*)&h23};
    *(uint2*)(out + (size_t)w * 128 + d0) = packed;
}

// ---------------------- aggregation (1 head x 64) + log_softmax ----------------------
__global__ __launch_bounds__(256) void k_agg1_lsm(
    const __half* __restrict__ H, const float* __restrict__ als,
    const float* __restrict__ ald, const float* __restrict__ bias,
    float* __restrict__ out, int n)
{
    int w = (blockIdx.x * blockDim.x + threadIdx.x) >> 5;
    if (w >= n) return;
    int lane = threadIdx.x & 31;
    int s = g_rowptr[w], e2 = g_rowptr[w + 1];
    float aldv = ald[w];
    int d0 = lane * 2;

    float denom = 0.f, acc0 = 0.f, acc1 = 0.f;
    int i = s;
    for (; i + 4 <= e2; i += 4) {
        int sv[4];
        #pragma unroll
        for (int j = 0; j < 4; j++) sv[j] = g_srcs[i + j];
        float wv[4];
        #pragma unroll
        for (int j = 0; j < 4; j++) {
            float x = als[sv[j]] + aldv;
            x = (x > 0.f) ? x : LRELU * x;
            wv[j] = __expf(x);
            denom += wv[j];
        }
        __half2 hv[4];
        #pragma unroll
        for (int j = 0; j < 4; j++) hv[j] = *(const __half2*)(H + (size_t)sv[j] * 64 + d0);
        #pragma unroll
        for (int j = 0; j < 4; j++) {
            float2 f = __half22float2(hv[j]);
            acc0 = fmaf(wv[j], f.x, acc0);
            acc1 = fmaf(wv[j], f.y, acc1);
        }
    }
    for (; i < e2; ++i) {
        int s0 = g_srcs[i];
        float x0 = als[s0] + aldv;
        x0 = (x0 > 0.f) ? x0 : LRELU * x0;
        float w0 = __expf(x0);
        denom += w0;
        float2 f = __half22float2(*(const __half2*)(H + (size_t)s0 * 64 + d0));
        acc0 = fmaf(w0, f.x, acc0); acc1 = fmaf(w0, f.y, acc1);
    }
    float inv = 1.f / denom;
    float v0 = fmaf(acc0, inv, bias[d0]);
    float v1 = fmaf(acc1, inv, bias[d0 + 1]);
    float mx = fmaxf(v0, v1);
    #pragma unroll
    for (int o = 16; o; o >>= 1) mx = fmaxf(mx, __shfl_xor_sync(0xFFFFFFFFu, mx, o));
    float se = __expf(v0 - mx) + __expf(v1 - mx);
    #pragma unroll
    for (int o = 16; o; o >>= 1) se += __shfl_xor_sync(0xFFFFFFFFu, se, o);
    float lse = mx + __logf(se);
    out[(size_t)w * 64 + d0] = v0 - lse;
    out[(size_t)w * 64 + d0 + 1] = v1 - lse;
}

// ---------------------- launcher ----------------------
extern "C" void kernel_launch(void* const* d_in, const int* in_sizes, int n_in,
                              void* d_out, int out_size) {
    const float* x   = (const float*)d_in[0];
    const int*   ei  = (const int*)d_in[1];
    const float* W0  = (const float*)d_in[2];
    const float* as0 = (const float*)d_in[3];
    const float* ad0 = (const float*)d_in[4];
    const float* b0  = (const float*)d_in[5];
    const float* W1  = (const float*)d_in[6];
    const float* as1 = (const float*)d_in[7];
    const float* ad1 = (const float*)d_in[8];
    const float* b1  = (const float*)d_in[9];
    const float* W2  = (const float*)d_in[10];
    const float* as2 = (const float*)d_in[11];
    const float* ad2 = (const float*)d_in[12];
    const float* b2  = (const float*)d_in[13];
    const float* ln1g = (const float*)d_in[14];
    const float* ln1b = (const float*)d_in[15];
    const float* ln2g = (const float*)d_in[16];
    const float* ln2b = (const float*)d_in[17];
    float* out = (float*)d_out;

    const int n = in_sizes[0] / 128;
    const int e = in_sizes[1] / 2;
    const int etot = e + n;
    const int* src = ei;
    const int* dst = ei + e;

    __half *h, *feat;
    float *als, *ald;
    cudaGetSymbolAddress((void**)&h, g_h);
    cudaGetSymbolAddress((void**)&feat, g_feat);
    cudaGetSymbolAddress((void**)&als, g_als);
    cudaGetSymbolAddress((void**)&ald, g_ald);

    const int nb_nodes256 = (n + 255) / 256;
    const int nb_edges256 = (e + 255) / 256;
    const int nb_scan = (n + 1023) / 1024;
    const int nb_warp = (n * 32 + 255) / 256;
    const int nb_gemm = (n + 127) / 128;

    k_init_cnt<<<nb_nodes256, 256>>>(n);
    k_count<<<nb_edges256, 256>>>(dst, e);
    k_scan1<<<nb_scan, 1024>>>(n);
    k_scan2<<<1, 128>>>(nb_scan);
    k_scan3<<<nb_scan, 1024>>>(n, etot);
    k_scatter<<<nb_edges256, 256>>>(src, dst, e);

    k_gemm_attn8_f16<float><<<nb_gemm, 256>>>(x, W0, as0, ad0, h, als, ald, n);
    k_agg8<<<nb_warp, 256>>>(h, als, ald, b0, ln1g, ln1b, feat, n);

    k_gemm_attn8_f16<__half><<<nb_gemm, 256>>>(feat, W1, as1, ad1, h, als, ald, n);
    k_agg8<<<nb_warp, 256>>>(h, als, ald, b1, ln2g, ln2b, feat, n);

    k_gemm_attn1_f16<<<nb_gemm, 256>>>(feat, W2, as2, ad2, h, als, ald, n);
    k_agg1_lsm<<<nb_warp, 256>>>(h, als, ald, b2, out, n);
}